// round 8
// baseline (speedup 1.0000x reference)
#include <cuda_runtime.h>
#include <math.h>

// Problem shape (fixed by reference)
#define BB 32
#define TT 2048
#define HE 1024
#define DEC_FLAT 2048

// Work decomposition
#define NW 64                   // warp work-units per batch
#define ROWS_PER_WARP (TT / NW) // 32 rows per warp
#define WPB 8                   // warps per block
#define GRID_MAIN (BB * NW / WPB) // 256 blocks -> single wave @ occ 2

// Scratch: __device__ globals (no allocation allowed)
__device__ float g_bias[BB];
__device__ float g_pm[BB * NW];
__device__ float g_ps[BB * NW];
__device__ float g_pacc[(size_t)BB * NW * HE]; // 8 MB

// ---------------------------------------------------------------------------
// Kernel 0: per-batch bias = hid_flat[b] . w_h + attn_b
// hidden layout (2, 32, 1024): hid_flat[b, l*1024+j] = hidden[l, b, j]
// ---------------------------------------------------------------------------
__global__ void attn_bias_kernel(const float* __restrict__ hidden,
                                 const float* __restrict__ attn_w,
                                 const float* __restrict__ attn_b) {
    int b = blockIdx.x;
    int tid = threadIdx.x;
    float sum = 0.f;
    const float* h0 = hidden + (size_t)b * HE;            // hidden[0, b, :]
    const float* h1 = hidden + (size_t)(BB + b) * HE;     // hidden[1, b, :]
    for (int j = tid; j < HE; j += 256) {
        sum += h0[j] * attn_w[j] + h1[j] * attn_w[HE + j];
    }
    __shared__ float sh[256];
    sh[tid] = sum;
    __syncthreads();
    for (int o = 128; o > 0; o >>= 1) {
        if (tid < o) sh[tid] += sh[tid + o];
        __syncthreads();
    }
    if (tid == 0) g_bias[b] = sh[0] + attn_b[0];
}

// ---------------------------------------------------------------------------
// Kernel 1: single-pass online-softmax weighted accumulation.
// One warp = one work unit: 32 rows of one batch. Per-warp partial (m, s, acc).
// ---------------------------------------------------------------------------
__global__ __launch_bounds__(256, 2)
void attn_main_kernel(const float* __restrict__ enc,
                      const float* __restrict__ mask,
                      const float* __restrict__ attn_w) {
    const int lane = threadIdx.x & 31;
    const int warp = blockIdx.x * WPB + (threadIdx.x >> 5);
    const int b = warp / NW;
    const int c = warp % NW;

    const float bias = g_bias[b];

    // w_e fragment: lane covers columns {i*128 + lane*4 .. +3}, i=0..7
    float4 wev[8], av[8];
#pragma unroll
    for (int i = 0; i < 8; i++) {
        wev[i] = *(const float4*)(attn_w + DEC_FLAT + i * 128 + lane * 4);
        av[i] = make_float4(0.f, 0.f, 0.f, 0.f);
    }

    float m = -INFINITY;
    float s = 0.f;

    const float* encb = enc + ((size_t)b * TT + (size_t)c * ROWS_PER_WARP) * HE;
    const float* maskb = mask + (size_t)b * TT + (size_t)c * ROWS_PER_WARP;

    for (int r = 0; r < ROWS_PER_WARP; r++) {
        const float4* rowp = (const float4*)(encb + (size_t)r * HE);
        float4 rv[8];
#pragma unroll
        for (int i = 0; i < 8; i++) rv[i] = rowp[i * 32 + lane]; // MLP=8

        float d = 0.f;
#pragma unroll
        for (int i = 0; i < 8; i++) {
            d = fmaf(rv[i].x, wev[i].x, d);
            d = fmaf(rv[i].y, wev[i].y, d);
            d = fmaf(rv[i].z, wev[i].z, d);
            d = fmaf(rv[i].w, wev[i].w, d);
        }
        // butterfly reduce: all lanes end with full dot
#pragma unroll
        for (int off = 16; off > 0; off >>= 1)
            d += __shfl_xor_sync(0xffffffffu, d, off);

        float mk = __ldg(maskb + r);
        float e = (d + bias) * mk;

        // online max (warp-uniform branch; taken O(log T) times)
        if (e > m) {
            float sc = __expf(m - e); // exp(-inf)=0 on first row: zeroes nothing
            s *= sc;
#pragma unroll
            for (int i = 0; i < 8; i++) {
                av[i].x *= sc; av[i].y *= sc; av[i].z *= sc; av[i].w *= sc;
            }
            m = e;
        }
        float p = __expf(e - m) * mk;
        s += p;
#pragma unroll
        for (int i = 0; i < 8; i++) {
            av[i].x = fmaf(p, rv[i].x, av[i].x);
            av[i].y = fmaf(p, rv[i].y, av[i].y);
            av[i].z = fmaf(p, rv[i].z, av[i].z);
            av[i].w = fmaf(p, rv[i].w, av[i].w);
        }
    }

    if (lane == 0) {
        g_pm[warp] = m;
        g_ps[warp] = s;
    }
    float4* outp = (float4*)(g_pacc + (size_t)warp * HE);
#pragma unroll
    for (int i = 0; i < 8; i++) outp[i * 32 + lane] = av[i];
}

// ---------------------------------------------------------------------------
// Kernel 2: combine NW partials per batch -> out[b, :]
// ---------------------------------------------------------------------------
__global__ void attn_reduce_kernel(float* __restrict__ out) {
    int b = blockIdx.x;
    int tid = threadIdx.x;

    __shared__ float s_scale[NW];
    __shared__ float s_invS;

    if (tid < NW) s_scale[tid] = g_pm[b * NW + tid];
    __syncthreads();

    if (tid == 0) {
        float M = -INFINITY;
        for (int c2 = 0; c2 < NW; c2++) M = fmaxf(M, s_scale[c2]);
        float S = 0.f;
        for (int c2 = 0; c2 < NW; c2++) {
            float sc = __expf(s_scale[c2] - M);
            s_scale[c2] = sc;
            S += sc * g_ps[b * NW + c2];
        }
        s_invS = 1.f / S;
    }
    __syncthreads();

    const float inv = s_invS;
    // thread tid owns columns [tid*4, tid*4+4)
    float4 acc = make_float4(0.f, 0.f, 0.f, 0.f);
    const float* base = g_pacc + (size_t)b * NW * HE + tid * 4;
#pragma unroll 4
    for (int c2 = 0; c2 < NW; c2++) {
        float sc = s_scale[c2];
        float4 v = *(const float4*)(base + (size_t)c2 * HE);
        acc.x = fmaf(sc, v.x, acc.x);
        acc.y = fmaf(sc, v.y, acc.y);
        acc.z = fmaf(sc, v.z, acc.z);
        acc.w = fmaf(sc, v.w, acc.w);
    }
    float4 o = make_float4(acc.x * inv, acc.y * inv, acc.z * inv, acc.w * inv);
    *(float4*)(out + (size_t)b * HE + tid * 4) = o;
}

// ---------------------------------------------------------------------------
// Entry point. Inputs (metadata order): hidden, encoder_outputs, mask,
// attn_w, attn_b. Output: (32, 1024) f32.
// ---------------------------------------------------------------------------
extern "C" void kernel_launch(void* const* d_in, const int* in_sizes, int n_in,
                              void* d_out, int out_size) {
    const float* hidden = (const float*)d_in[0];
    const float* enc    = (const float*)d_in[1];
    const float* mask   = (const float*)d_in[2];
    const float* attn_w = (const float*)d_in[3];
    const float* attn_b = (const float*)d_in[4];
    float* out = (float*)d_out;

    attn_bias_kernel<<<BB, 256>>>(hidden, attn_w, attn_b);
    attn_main_kernel<<<GRID_MAIN, 256>>>(enc, mask, attn_w);
    attn_reduce_kernel<<<BB, 256>>>(out);
}

// round 10
// speedup vs baseline: 1.1159x; 1.1159x over previous
#include <cuda_runtime.h>
#include <math.h>

// Problem shape (fixed by reference)
#define BB 32
#define TT 2048
#define HE 1024
#define DEC_FLAT 2048

// Work decomposition
#define NW 64                     // warp work-units per batch
#define ROWS_PER_WARP (TT / NW)   // 32 rows per warp
#define WPB 8                     // warps per block
#define BLOCKS_PER_B (NW / WPB)   // 8 blocks per batch
#define GRID_MAIN (BB * BLOCKS_PER_B) // 256 blocks -> single wave @ occ 2

// Scratch: __device__ globals (no allocation allowed)
__device__ float g_pm[BB * NW];
__device__ float g_ps[BB * NW];
__device__ float g_pacc[(size_t)BB * NW * HE]; // 8 MB
__device__ int   g_cnt[BB];                    // zero-init; reset by last block

// ---------------------------------------------------------------------------
// Fully fused kernel:
//   phase 0: per-block cooperative bias  (hid_flat[b] . w_h + attn_b)
//   phase 1: per-warp online-softmax weighted accumulation over 32 rows
//   phase 2: last-arriving block per batch combines the 64 partials
// ---------------------------------------------------------------------------
__global__ __launch_bounds__(256, 2)
void attn_fused_kernel(const float* __restrict__ hidden,
                       const float* __restrict__ enc,
                       const float* __restrict__ mask,
                       const float* __restrict__ attn_w,
                       const float* __restrict__ attn_b,
                       float* __restrict__ out) {
    const int tid  = threadIdx.x;
    const int lane = tid & 31;
    const int wid  = tid >> 5;
    const int b    = blockIdx.x / BLOCKS_PER_B;          // batch for this block
    const int c    = (blockIdx.x % BLOCKS_PER_B) * WPB + wid; // warp unit in batch
    const int warp = b * NW + c;

    __shared__ float sh[256];
    __shared__ float s_bias;
    __shared__ int   s_last;

    // ---- phase 0: bias = hid_flat[b] . w_h + attn_b (block-cooperative) ----
    {
        float sum = 0.f;
        const float* h0 = hidden + (size_t)b * HE;          // hidden[0, b, :]
        const float* h1 = hidden + (size_t)(BB + b) * HE;   // hidden[1, b, :]
#pragma unroll
        for (int j = tid; j < HE; j += 256)
            sum += h0[j] * attn_w[j] + h1[j] * attn_w[HE + j];
        sh[tid] = sum;
        __syncthreads();
        for (int o = 128; o > 0; o >>= 1) {
            if (tid < o) sh[tid] += sh[tid + o];
            __syncthreads();
        }
        if (tid == 0) s_bias = sh[0] + attn_b[0];
        __syncthreads();
    }
    const float bias = s_bias;

    // ---- phase 1: online-softmax weighted accumulation (per warp) ----
    // w_e fragment: lane covers columns {i*128 + lane*4 .. +3}, i=0..7
    float4 wev[8], av[8];
#pragma unroll
    for (int i = 0; i < 8; i++) {
        wev[i] = *(const float4*)(attn_w + DEC_FLAT + i * 128 + lane * 4);
        av[i] = make_float4(0.f, 0.f, 0.f, 0.f);
    }

    float m = -INFINITY;
    float s = 0.f;

    const float* encb  = enc + ((size_t)b * TT + (size_t)c * ROWS_PER_WARP) * HE;
    const float* maskb = mask + (size_t)b * TT + (size_t)c * ROWS_PER_WARP;

    for (int r = 0; r < ROWS_PER_WARP; r++) {
        const float4* rowp = (const float4*)(encb + (size_t)r * HE);
        float4 rv[8];
#pragma unroll
        for (int i = 0; i < 8; i++) rv[i] = rowp[i * 32 + lane]; // MLP=8

        float d = 0.f;
#pragma unroll
        for (int i = 0; i < 8; i++) {
            d = fmaf(rv[i].x, wev[i].x, d);
            d = fmaf(rv[i].y, wev[i].y, d);
            d = fmaf(rv[i].z, wev[i].z, d);
            d = fmaf(rv[i].w, wev[i].w, d);
        }
#pragma unroll
        for (int off = 16; off > 0; off >>= 1)
            d += __shfl_xor_sync(0xffffffffu, d, off);

        float mk = __ldg(maskb + r);
        float e = (d + bias) * mk;

        if (e > m) {                 // warp-uniform, taken O(log T) times
            float sc = __expf(m - e);
            s *= sc;
#pragma unroll
            for (int i = 0; i < 8; i++) {
                av[i].x *= sc; av[i].y *= sc; av[i].z *= sc; av[i].w *= sc;
            }
            m = e;
        }
        float p = __expf(e - m) * mk;
        s += p;
#pragma unroll
        for (int i = 0; i < 8; i++) {
            av[i].x = fmaf(p, rv[i].x, av[i].x);
            av[i].y = fmaf(p, rv[i].y, av[i].y);
            av[i].z = fmaf(p, rv[i].z, av[i].z);
            av[i].w = fmaf(p, rv[i].w, av[i].w);
        }
    }

    if (lane == 0) {
        g_pm[warp] = m;
        g_ps[warp] = s;
    }
    float4* outp = (float4*)(g_pacc + (size_t)warp * HE);
#pragma unroll
    for (int i = 0; i < 8; i++) outp[i * 32 + lane] = av[i];

    // ---- phase 2: last block for this batch combines the partials ----
    __threadfence();                       // publish partials before arrival
    __syncthreads();                       // all warps' stores issued
    if (tid == 0) {
        int prev = atomicAdd(&g_cnt[b], 1);
        s_last = (prev == BLOCKS_PER_B - 1);
    }
    __syncthreads();
    if (!s_last) return;

    // Reuse sh[] for per-partial scales.
    __shared__ float s_invS;
    if (tid < NW) sh[tid] = g_pm[b * NW + tid];
    __syncthreads();
    if (tid == 0) {
        float M = -INFINITY;
        for (int k = 0; k < NW; k++) M = fmaxf(M, sh[k]);
        float S = 0.f;
        for (int k = 0; k < NW; k++) {
            float sc = __expf(sh[k] - M);
            sh[k] = sc;
            S += sc * g_ps[b * NW + k];
        }
        s_invS = 1.f / S;
        g_cnt[b] = 0;                      // reset for next graph replay
    }
    __syncthreads();

    const float inv = s_invS;
    // thread tid owns columns [tid*4, tid*4+4)
    float4 acc = make_float4(0.f, 0.f, 0.f, 0.f);
    const float* base = g_pacc + (size_t)b * NW * HE + tid * 4;
#pragma unroll 4
    for (int k = 0; k < NW; k++) {
        float sc = sh[k];
        float4 v = *(const float4*)(base + (size_t)k * HE);
        acc.x = fmaf(sc, v.x, acc.x);
        acc.y = fmaf(sc, v.y, acc.y);
        acc.z = fmaf(sc, v.z, acc.z);
        acc.w = fmaf(sc, v.w, acc.w);
    }
    *(float4*)(out + (size_t)b * HE + tid * 4) =
        make_float4(acc.x * inv, acc.y * inv, acc.z * inv, acc.w * inv);
}

// ---------------------------------------------------------------------------
// Entry point. Inputs (metadata order): hidden, encoder_outputs, mask,
// attn_w, attn_b. Output: (32, 1024) f32.
// ---------------------------------------------------------------------------
extern "C" void kernel_launch(void* const* d_in, const int* in_sizes, int n_in,
                              void* d_out, int out_size) {
    const float* hidden = (const float*)d_in[0];
    const float* enc    = (const float*)d_in[1];
    const float* mask   = (const float*)d_in[2];
    const float* attn_w = (const float*)d_in[3];
    const float* attn_b = (const float*)d_in[4];
    float* out = (float*)d_out;

    attn_fused_kernel<<<GRID_MAIN, 256>>>(hidden, enc, mask, attn_w, attn_b, out);
}